// round 15
// baseline (speedup 1.0000x reference)
#include <cuda_runtime.h>
#include <stdint.h>
#include <math.h>

#define BB 8
#define NPTS 2048
#define SSD 1024
#define GGR 30
#define TITERS 10
#define TOT1 (BB*NPTS)
#define ROWS (BB*SSD)
#define RPB 4            // rows per block in k_group
#define FS 32            // seeds per block in k_fit

__device__ float d_wsoft[TOT1];
__device__ float d_logw[TOT1];
__device__ float d_seed_src[TITERS*BB*3*SSD];
__device__ float d_seed_corr[TITERS*BB*3*SSD];
__device__ float d_seed_w[TITERS*BB*SSD];
__device__ int   d_nn[TITERS*ROWS*GGR];
__device__ float d_Rm[TITERS*ROWS*9];
__device__ float d_tv[TITERS*ROWS*3];
__device__ int   d_fit[TITERS*ROWS];

// ---------- JAX threefry2x32 (exact) ----------
__host__ __device__ __forceinline__ uint32_t rotl32(uint32_t x, int r){
  return (x<<r)|(x>>(32-r));
}
__host__ __device__ __forceinline__ void tf2x32(uint32_t k0,uint32_t k1,
    uint32_t x0,uint32_t x1,uint32_t&o0,uint32_t&o1){
  uint32_t ks2=k0^k1^0x1BD11BDAu;
  x0+=k0; x1+=k1;
#define TFR(r) { x0+=x1; x1=rotl32(x1,(r)); x1^=x0; }
  TFR(13)TFR(15)TFR(26)TFR(6)   x0+=k1;  x1+=ks2+1u;
  TFR(17)TFR(29)TFR(16)TFR(24)  x0+=ks2; x1+=k0+2u;
  TFR(13)TFR(15)TFR(26)TFR(6)   x0+=k0;  x1+=k1+3u;
  TFR(17)TFR(29)TFR(16)TFR(24)  x0+=k1;  x1+=ks2+4u;
  TFR(13)TFR(15)TFR(26)TFR(6)   x0+=ks2; x1+=k0+5u;
#undef TFR
  o0=x0; o1=x1;
}
// derive per-iteration subkey: key(42) --fold_in(it)--> F --split--> child j
__device__ __forceinline__ void iter_key(int it, int j, uint32_t&ka, uint32_t&kb){
  uint32_t f0,f1;
  tf2x32(0u,42u, 0u,(uint32_t)it, f0,f1);
  tf2x32(f0,f1, 0u,(uint32_t)j, ka,kb);
}
__device__ __forceinline__ uint32_t pbits(uint32_t k0,uint32_t k1,uint32_t idx){
  uint32_t a,b; tf2x32(k0,k1,0u,idx,a,b); return a^b;
}
__device__ __forceinline__ float gumbel_from_bits(uint32_t b){
  float f = __uint_as_float((b>>9)|0x3F800000u) - 1.0f;
  float u = fmaxf(1e-9f, f + 1e-9f);
  return -logf(-logf(u));
}
__device__ __forceinline__ uint32_t f2mono(float v){
  uint32_t bits = __float_as_uint(v);
  return (bits & 0x80000000u) ? ~bits : (bits ^ 0x80000000u);
}

// ---------- kernel 0: sanitize + softmax + log ----------
__global__ void k_softmax(const float* __restrict__ wts){
  int b = blockIdx.x, tid = threadIdx.x;
  __shared__ float red[256];
  float mx = -INFINITY;
  for(int n=tid;n<NPTS;n+=256){
    float v = wts[b*NPTS+n];
    if (isnan(v)) v = 1e-7f;
    if (isinf(v)) v = 1.0f;
    d_wsoft[b*NPTS+n] = v;
    mx = fmaxf(mx, v);
  }
  red[tid]=mx; __syncthreads();
  for(int s=128;s>0;s>>=1){ if(tid<s) red[tid]=fmaxf(red[tid],red[tid+s]); __syncthreads(); }
  mx = red[0]; __syncthreads();
  float sum=0.f;
  for(int n=tid;n<NPTS;n+=256){
    float e = expf(d_wsoft[b*NPTS+n]-mx);
    d_wsoft[b*NPTS+n]=e; sum+=e;
  }
  red[tid]=sum; __syncthreads();
  for(int s=128;s>0;s>>=1){ if(tid<s) red[tid]+=red[tid+s]; __syncthreads(); }
  sum = red[0];
  for(int n=tid;n<NPTS;n+=256){
    float p = __fdiv_rn(d_wsoft[b*NPTS+n], sum);
    d_wsoft[b*NPTS+n]=p;
    d_logw[b*NPTS+n]=logf(p);
  }
}

// ---------- all-iterations: gumbel scores + per-batch top-1024 bitonic ----------
__global__ void k_seedtopk(const float* __restrict__ src, const float* __restrict__ tgt){
  __shared__ unsigned long long key[NPTS];
  int it = blockIdx.x >> 3;            // grid = TITERS*BB
  int b  = blockIdx.x & 7;
  int tid = threadIdx.x;               // 1024
  uint32_t k0,k1; iter_key(it,0,k0,k1);
  for(int n=tid;n<NPTS;n+=1024){
    int gi = b*NPTS+n;
    float sc = d_logw[gi] + gumbel_from_bits(pbits(k0,k1,(uint32_t)gi));
    uint32_t mono = f2mono(sc);
    key[n] = (((unsigned long long)(~mono))<<32) | (uint32_t)n;
  }
  __syncthreads();
  for(int kk=2;kk<=NPTS;kk<<=1){
    for(int j=kk>>1;j>0;j>>=1){
      for(int i=tid;i<NPTS;i+=1024){
        int ixj=i^j;
        if(ixj>i){
          bool up = ((i&kk)==0);
          unsigned long long a=key[i], c=key[ixj];
          if((a>c)==up){ key[i]=c; key[ixj]=a; }
        }
      }
      __syncthreads();
    }
  }
  {
    int s = tid;
    int idx = (int)(key[s] & 0xFFFFFFFFull);
    int ib = it*BB + b;
    d_seed_w[ib*SSD+s] = d_wsoft[b*NPTS+idx];
    for(int c=0;c<3;c++){
      d_seed_src [(ib*3+c)*SSD+s] = src[(b*3+c)*NPTS+idx];
      d_seed_corr[(ib*3+c)*SSD+s] = tgt[(b*3+c)*NPTS+idx];
    }
  }
}

// ---------- all-iterations: consensus + rowsum + gumbel score + radix top-30 ----------
__global__ void k_group(){
  __shared__ float sx[SSD],sy[SSD],sz[SSD],cx[SSD],cy[SSD],cz[SSD]; // 24KB
  __shared__ uint32_t skey[SSD];                                    // 4KB
  __shared__ float red[256];
  __shared__ int hist[256];
  __shared__ int wtot8[8];
  __shared__ int ssel, sneed, scntgt, scnteq;
  int it   = blockIdx.x >> 11;         // grid = TITERS*(ROWS/RPB) = TITERS*2048
  int blk2 = blockIdx.x & 2047;
  int b  = blk2 >> 8;                  // SSD/RPB = 256
  int rt = blk2 & 255;
  int tid=threadIdx.x;                 // 256
  int lane = tid&31, w = tid>>5;
  uint32_t k0,k1; iter_key(it,1,k0,k1);
  int ib = it*BB + b;
  for(int j=tid;j<SSD;j+=256){
    sx[j]=d_seed_src [(ib*3+0)*SSD+j];
    sy[j]=d_seed_src [(ib*3+1)*SSD+j];
    sz[j]=d_seed_src [(ib*3+2)*SSD+j];
    cx[j]=d_seed_corr[(ib*3+0)*SSD+j];
    cy[j]=d_seed_corr[(ib*3+1)*SSD+j];
    cz[j]=d_seed_corr[(ib*3+2)*SSD+j];
  }
  __syncthreads();
  for(int r=0;r<RPB;r++){
    int i = rt*RPB + r;
    int row = b*SSD + i;               // within-iteration row (pbits index base)
    float six=sx[i],siy=sy[i],siz=sz[i],cix=cx[i],ciy=cy[i],ciz=cz[i];
    float cc[4];
    float sum=0.f;
    #pragma unroll
    for(int k=0;k<4;k++){
      int j = tid + 256*k;
      float dxs=__fadd_rn(six,-sx[j]), dys=__fadd_rn(siy,-sy[j]), dzs=__fadd_rn(siz,-sz[j]);
      float ds = sqrtf(__fadd_rn(__fadd_rn(__fmul_rn(dxs,dxs),__fmul_rn(dys,dys)),__fmul_rn(dzs,dzs)));
      float dxc=__fadd_rn(cix,-cx[j]), dyc=__fadd_rn(ciy,-cy[j]), dzc=__fadd_rn(ciz,-cz[j]);
      float dc = sqrtf(__fadd_rn(__fadd_rn(__fmul_rn(dxc,dxc),__fmul_rn(dyc,dyc)),__fmul_rn(dzc,dzc)));
      float diff = __fadd_rn(ds,-dc);
      float c = expf(-__fdiv_rn(__fmul_rn(diff,diff), 0.01f));
      c = fmaxf(c, 0.1f);
      cc[k]=c; sum += c;
    }
    red[tid]=sum; __syncthreads();
    for(int s=128;s>0;s>>=1){ if(tid<s) red[tid]+=red[tid+s]; __syncthreads(); }
    float rowsum = red[0];
    uint32_t mk[4];
    #pragma unroll
    for(int k=0;k<4;k++){
      int j = tid + 256*k;
      float g = gumbel_from_bits(pbits(k0,k1,(uint32_t)(row*SSD+j)));
      float sc = logf(__fdiv_rn(cc[k], rowsum)) + g;
      mk[k] = f2mono(sc);
      skey[j] = mk[k];
    }
    uint32_t prefix=0, prefmask=0;
    int need=GGR;
    for(int lvl=0;lvl<4;lvl++){
      int shift = 24-8*lvl;
      hist[tid]=0;
      __syncthreads();
      #pragma unroll
      for(int k=0;k<4;k++){
        if((mk[k]&prefmask)==prefix) atomicAdd(&hist[(mk[k]>>shift)&255],1);
      }
      __syncthreads();
      int h = hist[tid];
      int val = h;
      #pragma unroll
      for(int off=1;off<32;off<<=1){
        int v2=__shfl_down_sync(0xffffffffu,val,off);
        if(lane+off<32) val+=v2;
      }
      if(lane==0) wtot8[w]=val;
      __syncthreads();
      if(tid<8){
        int v2=wtot8[tid];
        #pragma unroll
        for(int off=1;off<8;off<<=1){
          int t2=__shfl_down_sync(0xffu,v2,off);
          if(tid+off<8) v2+=t2;
        }
        wtot8[tid]=v2;
      }
      __syncthreads();
      int suffix = val + ((w<7)? wtot8[w+1] : 0);
      if(suffix>=need && suffix-h<need){ ssel=tid; sneed=need-(suffix-h); }
      __syncthreads();
      prefix |= ((uint32_t)ssel)<<shift;
      prefmask |= 0xFFu<<shift;
      need = sneed;
      __syncthreads();
    }
    if(tid==0){ scntgt=0; scnteq=0; }
    __syncthreads();
    int nnbase = (it*ROWS + row)*GGR;
    #pragma unroll
    for(int k=0;k<4;k++){
      if(mk[k]>prefix){ int slot=atomicAdd(&scntgt,1); d_nn[nnbase+slot]=tid+256*k; }
      else if(mk[k]==prefix){ atomicAdd(&scnteq,1); }
    }
    __syncthreads();
    if(scnteq==need){
      #pragma unroll
      for(int k=0;k<4;k++){
        if(mk[k]==prefix){ int slot=atomicAdd(&scntgt,1); d_nn[nnbase+slot]=tid+256*k; }
      }
    } else {
      if(tid==0){
        int base = GGR-need, c=0;
        for(int j=0;j<SSD && c<need;j++){
          if(skey[j]==prefix){ d_nn[nnbase+base+c]=j; c++; }
        }
      }
    }
    __syncthreads();
  }
}

// ---------- all-iterations: weighted Procrustes (fp32 Jacobi SVD) ----------
__global__ void k_proc(){
  int gid = blockIdx.x*blockDim.x + threadIdx.x;   // grid = TITERS*ROWS/32, block 32
  int it  = gid >> 13;                              // ROWS = 8192
  int row = gid & (ROWS-1);
  int ib = it*BB + (row>>10);
  const float* ssrc = &d_seed_src[ib*3*SSD];
  const float* scor = &d_seed_corr[ib*3*SSD];
  const float* sw   = &d_seed_w[ib*SSD];
  const int*   nnp  = &d_nn[((size_t)it*ROWS+row)*GGR];

  int nnr[GGR];
  #pragma unroll
  for(int g=0;g<GGR;g++) nnr[g]=nnp[g];

  float wsum=0.f,smx=0.f,smy=0.f,smz=0.f,cmx=0.f,cmy=0.f,cmz=0.f;
  #pragma unroll
  for(int g=0;g<GGR;g++){
    int j=nnr[g];
    wsum+=sw[j];
    smx+=ssrc[j]; smy+=ssrc[SSD+j]; smz+=ssrc[2*SSD+j];
    cmx+=scor[j]; cmy+=scor[SSD+j]; cmz+=scor[2*SSD+j];
  }
  smx/=30.f; smy/=30.f; smz/=30.f; cmx/=30.f; cmy/=30.f; cmz/=30.f;

  float H[3][3]={{0,0,0},{0,0,0},{0,0,0}};
  #pragma unroll
  for(int g=0;g<GGR;g++){
    int j=nnr[g];
    float wn=sw[j]/wsum;
    float ax=ssrc[j]-smx, ay=ssrc[SSD+j]-smy, az=ssrc[2*SSD+j]-smz;
    float bx=scor[j]-cmx, by=scor[SSD+j]-cmy, bz=scor[2*SSD+j]-cmz;
    float wax=wn*ax, way=wn*ay, waz=wn*az;
    H[0][0]+=wax*bx; H[0][1]+=wax*by; H[0][2]+=wax*bz;
    H[1][0]+=way*bx; H[1][1]+=way*by; H[1][2]+=way*bz;
    H[2][0]+=waz*bx; H[2][1]+=waz*by; H[2][2]+=waz*bz;
  }

  float A[3][3];
  #pragma unroll
  for(int a=0;a<3;a++)
    #pragma unroll
    for(int c=0;c<3;c++){
      float s=0.f;
      #pragma unroll
      for(int m=0;m<3;m++) s+=H[m][a]*H[m][c];
      A[a][c]=s;
    }
  float Vv[3][3]={{1,0,0},{0,1,0},{0,0,1}};
  for(int sweep=0;sweep<12;sweep++){
    float off=fabsf(A[0][1])+fabsf(A[0][2])+fabsf(A[1][2]);
    if(off < 1e-10f*(fabsf(A[0][0])+fabsf(A[1][1])+fabsf(A[2][2])+1e-30f)) break;
    #pragma unroll
    for(int pi=0;pi<3;pi++){
      int p = (pi==2)?1:0;
      int q = (pi==0)?1:2;
      float apq=A[p][q];
      if(apq==0.f) continue;
      float theta=(A[q][q]-A[p][p])/(2.f*apq);
      float tt=((theta>=0.f)?1.f:-1.f)/(fabsf(theta)+sqrtf(theta*theta+1.f));
      float c=1.f/sqrtf(tt*tt+1.f), s=tt*c;
      #pragma unroll
      for(int k=0;k<3;k++){
        float akp=A[k][p],akq=A[k][q];
        A[k][p]=c*akp-s*akq; A[k][q]=s*akp+c*akq;
      }
      #pragma unroll
      for(int k=0;k<3;k++){
        float apk=A[p][k],aqk=A[q][k];
        A[p][k]=c*apk-s*aqk; A[q][k]=s*apk+c*aqk;
      }
      #pragma unroll
      for(int k=0;k<3;k++){
        float vkp=Vv[k][p],vkq=Vv[k][q];
        Vv[k][p]=c*vkp-s*vkq; Vv[k][q]=s*vkp+c*vkq;
      }
    }
  }
  float l0=A[0][0],l1=A[1][1],l2=A[2][2],lt;
  int o0=0,o1=1,o2=2,tmp;
  if(l0<l1){tmp=o0;o0=o1;o1=tmp; lt=l0;l0=l1;l1=lt;}
  if(l0<l2){tmp=o0;o0=o2;o2=tmp; lt=l0;l0=l2;l2=lt;}
  if(l1<l2){tmp=o1;o1=o2;o2=tmp; lt=l1;l1=l2;l2=lt;}
  int ord[3]={o0,o1,o2};
  float vc[3][3];
  #pragma unroll
  for(int k=0;k<3;k++)
    #pragma unroll
    for(int i2=0;i2<3;i2++) vc[k][i2]=Vv[k][ord[i2]];

  float Uc[3][3];
  #pragma unroll
  for(int i2=0;i2<2;i2++){
    float ux=0,uy=0,uz=0;
    #pragma unroll
    for(int m=0;m<3;m++){ ux+=H[0][m]*vc[m][i2]; uy+=H[1][m]*vc[m][i2]; uz+=H[2][m]*vc[m][i2]; }
    float nrm=sqrtf(ux*ux+uy*uy+uz*uz);
    float inv=(nrm>1e-30f)?(1.f/nrm):0.f;
    Uc[0][i2]=ux*inv; Uc[1][i2]=uy*inv; Uc[2][i2]=uz*inv;
  }
  {
    float cxp=Uc[1][0]*Uc[2][1]-Uc[2][0]*Uc[1][1];
    float cyp=Uc[2][0]*Uc[0][1]-Uc[0][0]*Uc[2][1];
    float czp=Uc[0][0]*Uc[1][1]-Uc[1][0]*Uc[0][1];
    float nrm=sqrtf(cxp*cxp+cyp*cyp+czp*czp);
    float inv=(nrm>1e-30f)?(1.f/nrm):0.f;
    Uc[0][2]=cxp*inv; Uc[1][2]=cyp*inv; Uc[2][2]=czp*inv;
  }
  float detU = Uc[0][0]*(Uc[1][1]*Uc[2][2]-Uc[1][2]*Uc[2][1])
             - Uc[0][1]*(Uc[1][0]*Uc[2][2]-Uc[1][2]*Uc[2][0])
             + Uc[0][2]*(Uc[1][0]*Uc[2][1]-Uc[1][1]*Uc[2][0]);
  float detV = vc[0][0]*(vc[1][1]*vc[2][2]-vc[1][2]*vc[2][1])
             - vc[0][1]*(vc[1][0]*vc[2][2]-vc[1][2]*vc[2][0])
             + vc[0][2]*(vc[1][0]*vc[2][1]-vc[1][1]*vc[2][0]);
  float dd = (detU*detV >= 0.f) ? 1.f : -1.f;

  float R[3][3];
  #pragma unroll
  for(int a=0;a<3;a++)
    #pragma unroll
    for(int c=0;c<3;c++)
      R[a][c]=vc[a][0]*Uc[c][0]+vc[a][1]*Uc[c][1]+dd*vc[a][2]*Uc[c][2];
  float tx=-(R[0][0]*smx+R[0][1]*smy+R[0][2]*smz)+cmx;
  float ty=-(R[1][0]*smx+R[1][1]*smy+R[1][2]*smz)+cmy;
  float tz=-(R[2][0]*smx+R[2][1]*smy+R[2][2]*smz)+cmz;
  size_t ro = (size_t)it*ROWS + row;
  #pragma unroll
  for(int a=0;a<3;a++)
    #pragma unroll
    for(int c=0;c<3;c++) d_Rm[ro*9+a*3+c]=R[a][c];
  d_tv[ro*3+0]=tx; d_tv[ro*3+1]=ty; d_tv[ro*3+2]=tz;
}

// ---------- all-iterations: fitness counts (register-blocked, FS=32) ----------
__global__ void k_fit(const float* __restrict__ src, const float* __restrict__ tgt){
  __shared__ float s_s[3*NPTS];    // 24KB
  __shared__ float s_t[3*NPTS];    // 24KB
  __shared__ float s_RT[FS*12];
  __shared__ int s_cnt[FS];
  int it  = blockIdx.x >> 8;       // per-iter blocks = BB*(SSD/FS) = 256
  int rem = blockIdx.x & 255;
  int b  = rem >> 5;               // SSD/FS = 32
  int sg = rem & 31;
  int tid=threadIdx.x;             // 256
  int lane=tid&31;
  const float* sb = src + (size_t)b*3*NPTS;
  const float* tb = tgt + (size_t)b*3*NPTS;
  for(int i=tid;i<3*NPTS;i+=256){ s_s[i]=sb[i]; s_t[i]=tb[i]; }
  for(int i=tid;i<FS*12;i+=256){
    int s=i/12, e=i%12;
    size_t ro = (size_t)it*ROWS + b*SSD + sg*FS + s;
    s_RT[i] = (e<9) ? d_Rm[ro*9+e] : d_tv[ro*3+(e-9)];
  }
  if(tid<FS) s_cnt[tid]=0;
  __syncthreads();
  #pragma unroll
  for(int cs=0;cs<FS;cs+=4){
    float Rr[4][12];
    #pragma unroll
    for(int s=0;s<4;s++)
      #pragma unroll
      for(int e=0;e<12;e++) Rr[s][e]=s_RT[(cs+s)*12+e];
    int cnt[4]={0,0,0,0};
    for(int n=tid;n<NPTS;n+=256){
      float x=s_s[n], y=s_s[NPTS+n], z=s_s[2*NPTS+n];
      float tx=s_t[n], ty=s_t[NPTS+n], tz=s_t[2*NPTS+n];
      #pragma unroll
      for(int s=0;s<4;s++){
        float px=Rr[s][0]*x+Rr[s][1]*y+Rr[s][2]*z+Rr[s][9];
        float py=Rr[s][3]*x+Rr[s][4]*y+Rr[s][5]*z+Rr[s][10];
        float pz=Rr[s][6]*x+Rr[s][7]*y+Rr[s][8]*z+Rr[s][11];
        float dx=__fadd_rn(px,-tx), dy=__fadd_rn(py,-ty), dz=__fadd_rn(pz,-tz);
        float L = sqrtf(__fadd_rn(__fadd_rn(__fmul_rn(dx,dx),__fmul_rn(dy,dy)),__fmul_rn(dz,dz)));
        if (L < 0.1f) cnt[s]++;
      }
    }
    #pragma unroll
    for(int s=0;s<4;s++){
      int v=cnt[s];
      #pragma unroll
      for(int off=16;off>0;off>>=1) v+=__shfl_down_sync(0xffffffffu,v,off);
      if(lane==0) atomicAdd(&s_cnt[cs+s],v);
    }
  }
  __syncthreads();
  if(tid<FS) d_fit[(size_t)it*ROWS + b*SSD + sg*FS + tid] = s_cnt[tid];
}

// ---------- final: per-(it,batch) argmax + sequential (vv<dist) replay + output ----------
__global__ void k_final(float* __restrict__ out){
  __shared__ int sbcnt[TITERS*BB];
  __shared__ int sbidx[TITERS*BB];
  __shared__ int sbest;
  int tid=threadIdx.x;             // 256: warp b handles batch b
  int b = tid>>5, lane = tid&31;
  for(int it=0; it<TITERS; it++){
    int bestc=-1, besti=0;
    for(int s=lane;s<SSD;s+=32){
      int c=d_fit[(size_t)it*ROWS + b*SSD + s];
      if(c>bestc){bestc=c;besti=s;}
    }
    for(int o=16;o>0;o>>=1){
      int oc=__shfl_down_sync(0xffffffffu,bestc,o);
      int oi=__shfl_down_sync(0xffffffffu,besti,o);
      if(oc>bestc || (oc==bestc && oi<besti)){bestc=oc;besti=oi;}
    }
    if(lane==0){ sbcnt[it*BB+b]=bestc; sbidx[it*BB+b]=besti; }
  }
  __syncthreads();
  if(tid==0){
    float dist=1e8f; int bi=0;
    for(int it=0; it<TITERS; it++){
      float sum=0.f;
      for(int i=0;i<BB;i++) sum += (float)sbcnt[it*BB+i]/2048.0f;
      float vv = sum/8.0f;
      if(vv<dist){ dist=vv; bi=it; }
    }
    sbest=bi;
  }
  __syncthreads();
  int bi=sbest;
  if(tid<BB*9){
    int b3=tid/9, e=tid%9;
    size_t ro = (size_t)bi*ROWS + b3*SSD + sbidx[bi*BB+b3];
    out[tid]=d_Rm[ro*9+e];
  } else if(tid<BB*9+BB*3){
    int t2=tid-BB*9; int b3=t2/3, e=t2%3;
    size_t ro = (size_t)bi*ROWS + b3*SSD + sbidx[bi*BB+b3];
    out[tid]=d_tv[ro*3+e];
  }
}

// ---------- host ----------
extern "C" void kernel_launch(void* const* d_in, const int* in_sizes, int n_in,
                              void* d_out, int out_size){
  const float* src=(const float*)d_in[0];
  const float* tgt=(const float*)d_in[1];
  const float* wts=(const float*)d_in[2];
  float* out=(float*)d_out;
  (void)in_sizes; (void)n_in; (void)out_size;

  k_softmax <<<BB,256>>>(wts);
  k_seedtopk<<<TITERS*BB,1024>>>(src,tgt);
  k_group   <<<TITERS*(ROWS/RPB),256>>>();
  k_proc    <<<TITERS*ROWS/32,32>>>();
  k_fit     <<<TITERS*BB*(SSD/FS),256>>>(src,tgt);
  k_final   <<<1,256>>>(out);
}

// round 16
// speedup vs baseline: 1.5808x; 1.5808x over previous
#include <cuda_runtime.h>
#include <stdint.h>
#include <math.h>

#define BB 8
#define NPTS 2048
#define SSD 1024
#define GGR 30
#define TITERS 10
#define TOT1 (BB*NPTS)
#define ROWS (BB*SSD)
#define RPB 4            // rows per block in k_group
#define FS 16            // seeds per block in k_fit (round-14 proven value)

__device__ float d_wsoft[TOT1];
__device__ float d_logw[TOT1];
__device__ float d_seed_src[TITERS*BB*3*SSD];
__device__ float d_seed_corr[TITERS*BB*3*SSD];
__device__ float d_seed_w[TITERS*BB*SSD];
__device__ int   d_nn[TITERS*ROWS*GGR];
__device__ float d_Rm[TITERS*ROWS*9];
__device__ float d_tv[TITERS*ROWS*3];
__device__ int   d_fit[TITERS*ROWS];

// ---------- JAX threefry2x32 (exact) ----------
__host__ __device__ __forceinline__ uint32_t rotl32(uint32_t x, int r){
  return (x<<r)|(x>>(32-r));
}
__host__ __device__ __forceinline__ void tf2x32(uint32_t k0,uint32_t k1,
    uint32_t x0,uint32_t x1,uint32_t&o0,uint32_t&o1){
  uint32_t ks2=k0^k1^0x1BD11BDAu;
  x0+=k0; x1+=k1;
#define TFR(r) { x0+=x1; x1=rotl32(x1,(r)); x1^=x0; }
  TFR(13)TFR(15)TFR(26)TFR(6)   x0+=k1;  x1+=ks2+1u;
  TFR(17)TFR(29)TFR(16)TFR(24)  x0+=ks2; x1+=k0+2u;
  TFR(13)TFR(15)TFR(26)TFR(6)   x0+=k0;  x1+=k1+3u;
  TFR(17)TFR(29)TFR(16)TFR(24)  x0+=k1;  x1+=ks2+4u;
  TFR(13)TFR(15)TFR(26)TFR(6)   x0+=ks2; x1+=k0+5u;
#undef TFR
  o0=x0; o1=x1;
}
// per-iteration subkey: key(42) --fold_in(it)--> F --split--> child j
__host__ __device__ __forceinline__ void iter_key(int it, int j, uint32_t&ka, uint32_t&kb){
  uint32_t f0,f1;
  tf2x32(0u,42u, 0u,(uint32_t)it, f0,f1);
  tf2x32(f0,f1, 0u,(uint32_t)j, ka,kb);
}
__device__ __forceinline__ uint32_t pbits(uint32_t k0,uint32_t k1,uint32_t idx){
  uint32_t a,b; tf2x32(k0,k1,0u,idx,a,b); return a^b;
}
__device__ __forceinline__ float gumbel_from_bits(uint32_t b){
  float f = __uint_as_float((b>>9)|0x3F800000u) - 1.0f;
  float u = fmaxf(1e-9f, f + 1e-9f);
  return -logf(-logf(u));
}
__device__ __forceinline__ uint32_t f2mono(float v){
  uint32_t bits = __float_as_uint(v);
  return (bits & 0x80000000u) ? ~bits : (bits ^ 0x80000000u);
}

// ---------- kernel 0: sanitize + softmax + log ----------
__global__ void k_softmax(const float* __restrict__ wts){
  int b = blockIdx.x, tid = threadIdx.x;
  __shared__ float red[256];
  float mx = -INFINITY;
  for(int n=tid;n<NPTS;n+=256){
    float v = wts[b*NPTS+n];
    if (isnan(v)) v = 1e-7f;
    if (isinf(v)) v = 1.0f;
    d_wsoft[b*NPTS+n] = v;
    mx = fmaxf(mx, v);
  }
  red[tid]=mx; __syncthreads();
  for(int s=128;s>0;s>>=1){ if(tid<s) red[tid]=fmaxf(red[tid],red[tid+s]); __syncthreads(); }
  mx = red[0]; __syncthreads();
  float sum=0.f;
  for(int n=tid;n<NPTS;n+=256){
    float e = expf(d_wsoft[b*NPTS+n]-mx);
    d_wsoft[b*NPTS+n]=e; sum+=e;
  }
  red[tid]=sum; __syncthreads();
  for(int s=128;s>0;s>>=1){ if(tid<s) red[tid]+=red[tid+s]; __syncthreads(); }
  sum = red[0];
  for(int n=tid;n<NPTS;n+=256){
    float p = __fdiv_rn(d_wsoft[b*NPTS+n], sum);
    d_wsoft[b*NPTS+n]=p;
    d_logw[b*NPTS+n]=logf(p);
  }
}

// ---------- all-iterations: gumbel scores + per-batch top-1024 bitonic (hoisted) ----------
__global__ void k_seedtopk(const float* __restrict__ src, const float* __restrict__ tgt){
  __shared__ unsigned long long key[NPTS];
  int it = blockIdx.x >> 3;            // grid = TITERS*BB
  int b  = blockIdx.x & 7;
  int tid = threadIdx.x;               // 1024
  uint32_t k0,k1; iter_key(it,0,k0,k1);
  for(int n=tid;n<NPTS;n+=1024){
    int gi = b*NPTS+n;
    float sc = d_logw[gi] + gumbel_from_bits(pbits(k0,k1,(uint32_t)gi));
    uint32_t mono = f2mono(sc);
    key[n] = (((unsigned long long)(~mono))<<32) | (uint32_t)n;
  }
  __syncthreads();
  for(int kk=2;kk<=NPTS;kk<<=1){
    for(int j=kk>>1;j>0;j>>=1){
      for(int i=tid;i<NPTS;i+=1024){
        int ixj=i^j;
        if(ixj>i){
          bool up = ((i&kk)==0);
          unsigned long long a=key[i], c=key[ixj];
          if((a>c)==up){ key[i]=c; key[ixj]=a; }
        }
      }
      __syncthreads();
    }
  }
  {
    int s = tid;
    int idx = (int)(key[s] & 0xFFFFFFFFull);
    int ib = it*BB + b;
    d_seed_w[ib*SSD+s] = d_wsoft[b*NPTS+idx];
    for(int c=0;c<3;c++){
      d_seed_src [(ib*3+c)*SSD+s] = src[(b*3+c)*NPTS+idx];
      d_seed_corr[(ib*3+c)*SSD+s] = tgt[(b*3+c)*NPTS+idx];
    }
  }
}

// ---------- per-iteration: consensus + rowsum + gumbel score + radix top-30 (round-14 body) ----------
__global__ void k_group(int it, uint32_t k0, uint32_t k1){
  __shared__ float sx[SSD],sy[SSD],sz[SSD],cx[SSD],cy[SSD],cz[SSD]; // 24KB
  __shared__ uint32_t skey[SSD];                                    // 4KB (rare tie path)
  __shared__ float red[256];
  __shared__ int hist[256];
  __shared__ int wtot8[8];
  __shared__ int ssel, sneed, scntgt, scnteq;
  int blk=blockIdx.x;                 // ROWS/RPB = 2048
  int b  = blk >> 8;                  // SSD/RPB = 256
  int rt = blk & 255;
  int tid=threadIdx.x;                // 256
  int lane = tid&31, w = tid>>5;
  int ib = it*BB + b;
  for(int j=tid;j<SSD;j+=256){
    sx[j]=d_seed_src [(ib*3+0)*SSD+j];
    sy[j]=d_seed_src [(ib*3+1)*SSD+j];
    sz[j]=d_seed_src [(ib*3+2)*SSD+j];
    cx[j]=d_seed_corr[(ib*3+0)*SSD+j];
    cy[j]=d_seed_corr[(ib*3+1)*SSD+j];
    cz[j]=d_seed_corr[(ib*3+2)*SSD+j];
  }
  __syncthreads();
  for(int r=0;r<RPB;r++){
    int i = rt*RPB + r;
    int row = b*SSD + i;              // within-iteration row (pbits index base)
    float six=sx[i],siy=sy[i],siz=sz[i],cix=cx[i],ciy=cy[i],ciz=cz[i];
    float cc[4];
    float sum=0.f;
    #pragma unroll
    for(int k=0;k<4;k++){
      int j = tid + 256*k;
      float dxs=__fadd_rn(six,-sx[j]), dys=__fadd_rn(siy,-sy[j]), dzs=__fadd_rn(siz,-sz[j]);
      float ds = sqrtf(__fadd_rn(__fadd_rn(__fmul_rn(dxs,dxs),__fmul_rn(dys,dys)),__fmul_rn(dzs,dzs)));
      float dxc=__fadd_rn(cix,-cx[j]), dyc=__fadd_rn(ciy,-cy[j]), dzc=__fadd_rn(ciz,-cz[j]);
      float dc = sqrtf(__fadd_rn(__fadd_rn(__fmul_rn(dxc,dxc),__fmul_rn(dyc,dyc)),__fmul_rn(dzc,dzc)));
      float diff = __fadd_rn(ds,-dc);
      float c = expf(-__fdiv_rn(__fmul_rn(diff,diff), 0.01f));
      c = fmaxf(c, 0.1f);
      cc[k]=c; sum += c;
    }
    red[tid]=sum; __syncthreads();
    for(int s=128;s>0;s>>=1){ if(tid<s) red[tid]+=red[tid+s]; __syncthreads(); }
    float rowsum = red[0];
    uint32_t mk[4];
    #pragma unroll
    for(int k=0;k<4;k++){
      int j = tid + 256*k;
      float g = gumbel_from_bits(pbits(k0,k1,(uint32_t)(row*SSD+j)));
      float sc = logf(__fdiv_rn(cc[k], rowsum)) + g;
      mk[k] = f2mono(sc);
      skey[j] = mk[k];
    }
    uint32_t prefix=0, prefmask=0;
    int need=GGR;
    for(int lvl=0;lvl<4;lvl++){
      int shift = 24-8*lvl;
      hist[tid]=0;
      __syncthreads();
      #pragma unroll
      for(int k=0;k<4;k++){
        if((mk[k]&prefmask)==prefix) atomicAdd(&hist[(mk[k]>>shift)&255],1);
      }
      __syncthreads();
      int h = hist[tid];
      int val = h;
      #pragma unroll
      for(int off=1;off<32;off<<=1){
        int v2=__shfl_down_sync(0xffffffffu,val,off);
        if(lane+off<32) val+=v2;
      }
      if(lane==0) wtot8[w]=val;
      __syncthreads();
      if(tid<8){
        int v2=wtot8[tid];
        #pragma unroll
        for(int off=1;off<8;off<<=1){
          int t2=__shfl_down_sync(0xffu,v2,off);
          if(tid+off<8) v2+=t2;
        }
        wtot8[tid]=v2;
      }
      __syncthreads();
      int suffix = val + ((w<7)? wtot8[w+1] : 0);
      if(suffix>=need && suffix-h<need){ ssel=tid; sneed=need-(suffix-h); }
      __syncthreads();
      prefix |= ((uint32_t)ssel)<<shift;
      prefmask |= 0xFFu<<shift;
      need = sneed;
      __syncthreads();
    }
    if(tid==0){ scntgt=0; scnteq=0; }
    __syncthreads();
    int nnbase = (it*ROWS + row)*GGR;
    #pragma unroll
    for(int k=0;k<4;k++){
      if(mk[k]>prefix){ int slot=atomicAdd(&scntgt,1); d_nn[nnbase+slot]=tid+256*k; }
      else if(mk[k]==prefix){ atomicAdd(&scnteq,1); }
    }
    __syncthreads();
    if(scnteq==need){
      #pragma unroll
      for(int k=0;k<4;k++){
        if(mk[k]==prefix){ int slot=atomicAdd(&scntgt,1); d_nn[nnbase+slot]=tid+256*k; }
      }
    } else {
      if(tid==0){
        int base = GGR-need, c=0;
        for(int j=0;j<SSD && c<need;j++){
          if(skey[j]==prefix){ d_nn[nnbase+base+c]=j; c++; }
        }
      }
    }
    __syncthreads();
  }
}

// ---------- all-iterations: weighted Procrustes (fp32 Jacobi SVD, flattened — measured win) ----------
__global__ void k_proc(){
  int gid = blockIdx.x*blockDim.x + threadIdx.x;   // grid = TITERS*ROWS/32, block 32
  int it  = gid >> 13;                              // ROWS = 8192
  int row = gid & (ROWS-1);
  int ib = it*BB + (row>>10);
  const float* ssrc = &d_seed_src[ib*3*SSD];
  const float* scor = &d_seed_corr[ib*3*SSD];
  const float* sw   = &d_seed_w[ib*SSD];
  const int*   nnp  = &d_nn[((size_t)it*ROWS+row)*GGR];

  int nnr[GGR];
  #pragma unroll
  for(int g=0;g<GGR;g++) nnr[g]=nnp[g];

  float wsum=0.f,smx=0.f,smy=0.f,smz=0.f,cmx=0.f,cmy=0.f,cmz=0.f;
  #pragma unroll
  for(int g=0;g<GGR;g++){
    int j=nnr[g];
    wsum+=sw[j];
    smx+=ssrc[j]; smy+=ssrc[SSD+j]; smz+=ssrc[2*SSD+j];
    cmx+=scor[j]; cmy+=scor[SSD+j]; cmz+=scor[2*SSD+j];
  }
  smx/=30.f; smy/=30.f; smz/=30.f; cmx/=30.f; cmy/=30.f; cmz/=30.f;

  float H[3][3]={{0,0,0},{0,0,0},{0,0,0}};
  #pragma unroll
  for(int g=0;g<GGR;g++){
    int j=nnr[g];
    float wn=sw[j]/wsum;
    float ax=ssrc[j]-smx, ay=ssrc[SSD+j]-smy, az=ssrc[2*SSD+j]-smz;
    float bx=scor[j]-cmx, by=scor[SSD+j]-cmy, bz=scor[2*SSD+j]-cmz;
    float wax=wn*ax, way=wn*ay, waz=wn*az;
    H[0][0]+=wax*bx; H[0][1]+=wax*by; H[0][2]+=wax*bz;
    H[1][0]+=way*bx; H[1][1]+=way*by; H[1][2]+=way*bz;
    H[2][0]+=waz*bx; H[2][1]+=waz*by; H[2][2]+=waz*bz;
  }

  float A[3][3];
  #pragma unroll
  for(int a=0;a<3;a++)
    #pragma unroll
    for(int c=0;c<3;c++){
      float s=0.f;
      #pragma unroll
      for(int m=0;m<3;m++) s+=H[m][a]*H[m][c];
      A[a][c]=s;
    }
  float Vv[3][3]={{1,0,0},{0,1,0},{0,0,1}};
  for(int sweep=0;sweep<12;sweep++){
    float off=fabsf(A[0][1])+fabsf(A[0][2])+fabsf(A[1][2]);
    if(off < 1e-10f*(fabsf(A[0][0])+fabsf(A[1][1])+fabsf(A[2][2])+1e-30f)) break;
    #pragma unroll
    for(int pi=0;pi<3;pi++){
      int p = (pi==2)?1:0;
      int q = (pi==0)?1:2;
      float apq=A[p][q];
      if(apq==0.f) continue;
      float theta=(A[q][q]-A[p][p])/(2.f*apq);
      float tt=((theta>=0.f)?1.f:-1.f)/(fabsf(theta)+sqrtf(theta*theta+1.f));
      float c=1.f/sqrtf(tt*tt+1.f), s=tt*c;
      #pragma unroll
      for(int k=0;k<3;k++){
        float akp=A[k][p],akq=A[k][q];
        A[k][p]=c*akp-s*akq; A[k][q]=s*akp+c*akq;
      }
      #pragma unroll
      for(int k=0;k<3;k++){
        float apk=A[p][k],aqk=A[q][k];
        A[p][k]=c*apk-s*aqk; A[q][k]=s*apk+c*aqk;
      }
      #pragma unroll
      for(int k=0;k<3;k++){
        float vkp=Vv[k][p],vkq=Vv[k][q];
        Vv[k][p]=c*vkp-s*vkq; Vv[k][q]=s*vkp+c*vkq;
      }
    }
  }
  float l0=A[0][0],l1=A[1][1],l2=A[2][2],lt;
  int o0=0,o1=1,o2=2,tmp;
  if(l0<l1){tmp=o0;o0=o1;o1=tmp; lt=l0;l0=l1;l1=lt;}
  if(l0<l2){tmp=o0;o0=o2;o2=tmp; lt=l0;l0=l2;l2=lt;}
  if(l1<l2){tmp=o1;o1=o2;o2=tmp; lt=l1;l1=l2;l2=lt;}
  int ord[3]={o0,o1,o2};
  float vc[3][3];
  #pragma unroll
  for(int k=0;k<3;k++)
    #pragma unroll
    for(int i2=0;i2<3;i2++) vc[k][i2]=Vv[k][ord[i2]];

  float Uc[3][3];
  #pragma unroll
  for(int i2=0;i2<2;i2++){
    float ux=0,uy=0,uz=0;
    #pragma unroll
    for(int m=0;m<3;m++){ ux+=H[0][m]*vc[m][i2]; uy+=H[1][m]*vc[m][i2]; uz+=H[2][m]*vc[m][i2]; }
    float nrm=sqrtf(ux*ux+uy*uy+uz*uz);
    float inv=(nrm>1e-30f)?(1.f/nrm):0.f;
    Uc[0][i2]=ux*inv; Uc[1][i2]=uy*inv; Uc[2][i2]=uz*inv;
  }
  {
    float cxp=Uc[1][0]*Uc[2][1]-Uc[2][0]*Uc[1][1];
    float cyp=Uc[2][0]*Uc[0][1]-Uc[0][0]*Uc[2][1];
    float czp=Uc[0][0]*Uc[1][1]-Uc[1][0]*Uc[0][1];
    float nrm=sqrtf(cxp*cxp+cyp*cyp+czp*czp);
    float inv=(nrm>1e-30f)?(1.f/nrm):0.f;
    Uc[0][2]=cxp*inv; Uc[1][2]=cyp*inv; Uc[2][2]=czp*inv;
  }
  float detU = Uc[0][0]*(Uc[1][1]*Uc[2][2]-Uc[1][2]*Uc[2][1])
             - Uc[0][1]*(Uc[1][0]*Uc[2][2]-Uc[1][2]*Uc[2][0])
             + Uc[0][2]*(Uc[1][0]*Uc[2][1]-Uc[1][1]*Uc[2][0]);
  float detV = vc[0][0]*(vc[1][1]*vc[2][2]-vc[1][2]*vc[2][1])
             - vc[0][1]*(vc[1][0]*vc[2][2]-vc[1][2]*vc[2][0])
             + vc[0][2]*(vc[1][0]*vc[2][1]-vc[1][1]*vc[2][0]);
  float dd = (detU*detV >= 0.f) ? 1.f : -1.f;

  float R[3][3];
  #pragma unroll
  for(int a=0;a<3;a++)
    #pragma unroll
    for(int c=0;c<3;c++)
      R[a][c]=vc[a][0]*Uc[c][0]+vc[a][1]*Uc[c][1]+dd*vc[a][2]*Uc[c][2];
  float tx=-(R[0][0]*smx+R[0][1]*smy+R[0][2]*smz)+cmx;
  float ty=-(R[1][0]*smx+R[1][1]*smy+R[1][2]*smz)+cmy;
  float tz=-(R[2][0]*smx+R[2][1]*smy+R[2][2]*smz)+cmz;
  size_t ro = (size_t)it*ROWS + row;
  #pragma unroll
  for(int a=0;a<3;a++)
    #pragma unroll
    for(int c=0;c<3;c++) d_Rm[ro*9+a*3+c]=R[a][c];
  d_tv[ro*3+0]=tx; d_tv[ro*3+1]=ty; d_tv[ro*3+2]=tz;
}

// ---------- all-iterations: fitness counts (FS=16, round-14 inner loop) ----------
__global__ void k_fit(const float* __restrict__ src, const float* __restrict__ tgt){
  __shared__ float s_s[3*NPTS];    // 24KB
  __shared__ float s_t[3*NPTS];    // 24KB
  __shared__ float s_RT[FS*12];
  __shared__ int s_cnt[FS];
  int it  = blockIdx.x >> 9;       // per-iter blocks = BB*(SSD/FS) = 512
  int rem = blockIdx.x & 511;
  int b  = rem >> 6;               // SSD/FS = 64
  int sg = rem & 63;
  int tid=threadIdx.x;             // 256
  int lane=tid&31;
  const float* sb = src + (size_t)b*3*NPTS;
  const float* tb = tgt + (size_t)b*3*NPTS;
  for(int i=tid;i<3*NPTS;i+=256){ s_s[i]=sb[i]; s_t[i]=tb[i]; }
  if(tid<FS*12){
    int s=tid/12, e=tid%12;
    size_t ro = (size_t)it*ROWS + b*SSD + sg*FS + s;
    s_RT[tid] = (e<9) ? d_Rm[ro*9+e] : d_tv[ro*3+(e-9)];
  }
  if(tid<FS) s_cnt[tid]=0;
  __syncthreads();
  #pragma unroll
  for(int cs=0;cs<FS;cs+=4){
    float Rr[4][12];
    #pragma unroll
    for(int s=0;s<4;s++)
      #pragma unroll
      for(int e=0;e<12;e++) Rr[s][e]=s_RT[(cs+s)*12+e];
    int cnt[4]={0,0,0,0};
    for(int n=tid;n<NPTS;n+=256){
      float x=s_s[n], y=s_s[NPTS+n], z=s_s[2*NPTS+n];
      float tx=s_t[n], ty=s_t[NPTS+n], tz=s_t[2*NPTS+n];
      #pragma unroll
      for(int s=0;s<4;s++){
        float px=Rr[s][0]*x+Rr[s][1]*y+Rr[s][2]*z+Rr[s][9];
        float py=Rr[s][3]*x+Rr[s][4]*y+Rr[s][5]*z+Rr[s][10];
        float pz=Rr[s][6]*x+Rr[s][7]*y+Rr[s][8]*z+Rr[s][11];
        float dx=__fadd_rn(px,-tx), dy=__fadd_rn(py,-ty), dz=__fadd_rn(pz,-tz);
        float L = sqrtf(__fadd_rn(__fadd_rn(__fmul_rn(dx,dx),__fmul_rn(dy,dy)),__fmul_rn(dz,dz)));
        if (L < 0.1f) cnt[s]++;
      }
    }
    #pragma unroll
    for(int s=0;s<4;s++){
      int v=cnt[s];
      #pragma unroll
      for(int off=16;off>0;off>>=1) v+=__shfl_down_sync(0xffffffffu,v,off);
      if(lane==0) atomicAdd(&s_cnt[cs+s],v);
    }
  }
  __syncthreads();
  if(tid<FS) d_fit[(size_t)it*ROWS + b*SSD + sg*FS + tid] = s_cnt[tid];
}

// ---------- final: per-(it,batch) argmax + sequential (vv<dist) replay + output ----------
__global__ void k_final(float* __restrict__ out){
  __shared__ int sbcnt[TITERS*BB];
  __shared__ int sbidx[TITERS*BB];
  __shared__ int sbest;
  int tid=threadIdx.x;             // 256: warp b handles batch b
  int b = tid>>5, lane = tid&31;
  for(int it=0; it<TITERS; it++){
    int bestc=-1, besti=0;
    for(int s=lane;s<SSD;s+=32){
      int c=d_fit[(size_t)it*ROWS + b*SSD + s];
      if(c>bestc){bestc=c;besti=s;}
    }
    for(int o=16;o>0;o>>=1){
      int oc=__shfl_down_sync(0xffffffffu,bestc,o);
      int oi=__shfl_down_sync(0xffffffffu,besti,o);
      if(oc>bestc || (oc==bestc && oi<besti)){bestc=oc;besti=oi;}
    }
    if(lane==0){ sbcnt[it*BB+b]=bestc; sbidx[it*BB+b]=besti; }
  }
  __syncthreads();
  if(tid==0){
    float dist=1e8f; int bi=0;
    for(int it=0; it<TITERS; it++){
      float sum=0.f;
      for(int i=0;i<BB;i++) sum += (float)sbcnt[it*BB+i]/2048.0f;
      float vv = sum/8.0f;
      if(vv<dist){ dist=vv; bi=it; }
    }
    sbest=bi;
  }
  __syncthreads();
  int bi=sbest;
  if(tid<BB*9){
    int b3=tid/9, e=tid%9;
    size_t ro = (size_t)bi*ROWS + b3*SSD + sbidx[bi*BB+b3];
    out[tid]=d_Rm[ro*9+e];
  } else if(tid<BB*9+BB*3){
    int t2=tid-BB*9; int b3=t2/3, e=t2%3;
    size_t ro = (size_t)bi*ROWS + b3*SSD + sbidx[bi*BB+b3];
    out[tid]=d_tv[ro*3+e];
  }
}

// ---------- host ----------
extern "C" void kernel_launch(void* const* d_in, const int* in_sizes, int n_in,
                              void* d_out, int out_size){
  const float* src=(const float*)d_in[0];
  const float* tgt=(const float*)d_in[1];
  const float* wts=(const float*)d_in[2];
  float* out=(float*)d_out;
  (void)in_sizes; (void)n_in; (void)out_size;

  k_softmax <<<BB,256>>>(wts);
  k_seedtopk<<<TITERS*BB,1024>>>(src,tgt);
  for (int it=0; it<TITERS; it++){
    uint32_t k2a,k2b; iter_key(it,1,k2a,k2b);
    k_group<<<ROWS/RPB,256>>>(it,k2a,k2b);
  }
  k_proc <<<TITERS*ROWS/32,32>>>();
  k_fit  <<<TITERS*BB*(SSD/FS),256>>>(src,tgt);
  k_final<<<1,256>>>(out);
}